// round 4
// baseline (speedup 1.0000x reference)
#include <cuda_runtime.h>
#include <cstdint>

#define D 128
#define MAX_N 100000
#define MAX_E 3200000
#define NSCAN 4096            // threads in the scan layer
#define TM 64                 // GEMM row tile

// ---------------------------------------------------------------------------
// Static device scratch (the sanctioned workaround for no-allocation rule)
// ---------------------------------------------------------------------------
__device__ int   g_is64;               // 1 if edge_index is int64, 0 if int32
__device__ int   g_cnt [MAX_N];        // in-degree histogram (no self loops)
__device__ int   g_ptr [MAX_N];        // CSR row starts
__device__ int   g_fill[MAX_N];        // fill cursors
__device__ int   g_srcs[MAX_E];        // src ids bucketed by dst
__device__ int   g_tsum[NSCAN];        // per-thread chunk sums
__device__ int   g_tbase[NSCAN];       // per-thread chunk exclusive prefixes
__device__ float g_dis [MAX_N];        // deg^-1/2 (deg includes self loop)
__device__ float g_hp  [(size_t)MAX_N * D];   // (x @ W^T) * dis[row]

// ---------------------------------------------------------------------------
// Edge accessors: p = edge_index viewed as raw int32 words.
// int32 layout: src[i] = p[i],          dst[i] = p[e + i]
// int64 layout: src[i] = p[2*i],        dst[i] = p[2*(e+i)]   (little-endian low word)
// ---------------------------------------------------------------------------
__device__ __forceinline__ int edge_src(const int* __restrict__ p, int is64, int e, int i) {
    return is64 ? p[2 * (size_t)i] : p[i];
}
__device__ __forceinline__ int edge_dst(const int* __restrict__ p, int is64, int e, int i) {
    return is64 ? p[2 * ((size_t)e + i)] : p[(size_t)e + i];
}

// ---------------------------------------------------------------------------
// 0. dtype detect: OR the odd 32-bit words of the first 2048 "int64 slots".
//    All zero -> int64 (values < 2^31). Any nonzero -> int32.
// ---------------------------------------------------------------------------
__global__ void detect_kernel(const int* __restrict__ p) {
    __shared__ int any;
    if (threadIdx.x == 0) any = 0;
    __syncthreads();
    int v = 0;
    for (int i = threadIdx.x; i < 2048; i += blockDim.x) v |= p[2 * i + 1];
    if (v) atomicOr(&any, 1);
    __syncthreads();
    if (threadIdx.x == 0) g_is64 = (any == 0) ? 1 : 0;
}

// ---------------------------------------------------------------------------
// 1. zero histogram
// ---------------------------------------------------------------------------
__global__ void zero_cnt_kernel(int n) {
    int i = blockIdx.x * blockDim.x + threadIdx.x;
    if (i < n) g_cnt[i] = 0;
}

// ---------------------------------------------------------------------------
// 2. histogram over dst (bounds-guarded)
// ---------------------------------------------------------------------------
__global__ void hist_kernel(const int* __restrict__ p, int e, int n) {
    int is64 = g_is64;
    int i = blockIdx.x * blockDim.x + threadIdx.x;
    int stride = gridDim.x * blockDim.x;
    for (; i < e; i += stride) {
        unsigned d = (unsigned)edge_dst(p, is64, e, i);
        if (d < (unsigned)n) atomicAdd(&g_cnt[d], 1);
    }
}

// ---------------------------------------------------------------------------
// 3. scan stage A: per-thread chunk sums (chunk = ceil(n/NSCAN))
// ---------------------------------------------------------------------------
__global__ void scanA_kernel(int n, int chunk) {
    int t = blockIdx.x * blockDim.x + threadIdx.x;
    if (t >= NSCAN) return;
    int b = t * chunk, eend = min(b + chunk, n);
    int s = 0;
    for (int i = b; i < eend; i++) s += g_cnt[i];
    g_tsum[t] = s;
}

// ---------------------------------------------------------------------------
// 4. scan stage B: exclusive scan of NSCAN sums (one block, 1024 threads x 4)
// ---------------------------------------------------------------------------
__global__ __launch_bounds__(1024) void scanB_kernel() {
    __shared__ int sh[1024];
    int t = threadIdx.x;
    int v0 = g_tsum[4 * t + 0], v1 = g_tsum[4 * t + 1];
    int v2 = g_tsum[4 * t + 2], v3 = g_tsum[4 * t + 3];
    int local = v0 + v1 + v2 + v3;
    sh[t] = local;
    __syncthreads();
    for (int off = 1; off < 1024; off <<= 1) {
        int add = (t >= off) ? sh[t - off] : 0;
        __syncthreads();
        sh[t] += add;
        __syncthreads();
    }
    int base = sh[t] - local;   // exclusive
    g_tbase[4 * t + 0] = base;
    g_tbase[4 * t + 1] = base + v0;
    g_tbase[4 * t + 2] = base + v0 + v1;
    g_tbase[4 * t + 3] = base + v0 + v1 + v2;
}

// ---------------------------------------------------------------------------
// 5. scan stage C: write row ptr, fill cursors, and dis = rsqrt(deg+1)
// ---------------------------------------------------------------------------
__global__ void scanC_kernel(int n, int chunk) {
    int t = blockIdx.x * blockDim.x + threadIdx.x;
    if (t >= NSCAN) return;
    int b = t * chunk, eend = min(b + chunk, n);
    int run = g_tbase[t];
    for (int i = b; i < eend; i++) {
        g_ptr[i] = run;
        g_fill[i] = run;
        int c = g_cnt[i];
        g_dis[i] = rsqrtf((float)(c + 1));   // +1 self loop
        run += c;
    }
}

// ---------------------------------------------------------------------------
// 6. fill: bucket src ids by dst (bounds-guarded)
// ---------------------------------------------------------------------------
__global__ void fill_kernel(const int* __restrict__ p, int e, int n) {
    int is64 = g_is64;
    int i = blockIdx.x * blockDim.x + threadIdx.x;
    int stride = gridDim.x * blockDim.x;
    for (; i < e; i += stride) {
        unsigned s = (unsigned)edge_src(p, is64, e, i);
        unsigned d = (unsigned)edge_dst(p, is64, e, i);
        if (d < (unsigned)n) {
            if (s >= (unsigned)n) s = 0;     // defensive clamp (never on valid data)
            int pos = atomicAdd(&g_fill[d], 1);
            if (pos < MAX_E) g_srcs[pos] = (int)s;
        }
    }
}

// ---------------------------------------------------------------------------
// 7. GEMM: g_hp[r][c] = (sum_k x[r][k] * w[c][k]) * g_dis[r]
//    256 thr, 64 rows x 128 cols per block, 8x4 register tile per thread.
// ---------------------------------------------------------------------------
__global__ __launch_bounds__(256) void gemm_kernel(
    const float* __restrict__ x, const float* __restrict__ w, int n)
{
    __shared__ float xs[TM][64];     // 16 KB
    __shared__ float wt[64][D];      // 32 KB

    const int tx = threadIdx.x & 31;
    const int ty = threadIdx.x >> 5;
    const int row0 = blockIdx.x * TM;

    float acc[8][4];
#pragma unroll
    for (int i = 0; i < 8; i++) { acc[i][0]=0.f; acc[i][1]=0.f; acc[i][2]=0.f; acc[i][3]=0.f; }

    for (int k0 = 0; k0 < D; k0 += 64) {
        for (int i = threadIdx.x; i < TM * 16; i += 256) {
            int r = i >> 4, q = i & 15;
            float4 v = make_float4(0.f, 0.f, 0.f, 0.f);
            if (row0 + r < n)
                v = ((const float4*)(x + (size_t)(row0 + r) * D + k0))[q];
            *(float4*)&xs[r][q * 4] = v;
        }
        for (int i = threadIdx.x; i < D * 16; i += 256) {
            int c = i >> 4, q = i & 15;
            float4 v = ((const float4*)(w + (size_t)c * D + k0))[q];
            wt[q * 4 + 0][c] = v.x;
            wt[q * 4 + 1][c] = v.y;
            wt[q * 4 + 2][c] = v.z;
            wt[q * 4 + 3][c] = v.w;
        }
        __syncthreads();

#pragma unroll
        for (int kk = 0; kk < 64; kk++) {
            float4 wv = *(const float4*)&wt[kk][tx * 4];
#pragma unroll
            for (int i = 0; i < 8; i++) {
                float xv = xs[ty + 8 * i][kk];
                acc[i][0] = fmaf(xv, wv.x, acc[i][0]);
                acc[i][1] = fmaf(xv, wv.y, acc[i][1]);
                acc[i][2] = fmaf(xv, wv.z, acc[i][2]);
                acc[i][3] = fmaf(xv, wv.w, acc[i][3]);
            }
        }
        __syncthreads();
    }

#pragma unroll
    for (int i = 0; i < 8; i++) {
        int r = row0 + ty + 8 * i;
        if (r < n) {
            float s = g_dis[r];
            float4 o = make_float4(acc[i][0]*s, acc[i][1]*s, acc[i][2]*s, acc[i][3]*s);
            *(float4*)&g_hp[(size_t)r * D + tx * 4] = o;
        }
    }
}

// ---------------------------------------------------------------------------
// 8. gather-aggregate: one warp per node.
//    out[d] = dis[d] * (hp[d] + sum_{s in srcs[d]} hp[s]) + bias
// ---------------------------------------------------------------------------
__global__ __launch_bounds__(256) void aggregate_kernel(
    const float* __restrict__ bias, float* __restrict__ out, int n)
{
    int warp = (blockIdx.x * blockDim.x + threadIdx.x) >> 5;
    int lane = threadIdx.x & 31;
    if (warp >= n) return;

    const float4* hpv = (const float4*)g_hp;
    int start = g_ptr[warp];
    int k = g_cnt[warp];

    float4 a0 = hpv[(size_t)warp * 32 + lane];      // self-loop term
    float4 a1 = make_float4(0.f, 0.f, 0.f, 0.f);

    int full = k & ~31;
    int j = 0;
    for (; j < full; j += 32) {
        int my = g_srcs[start + j + lane];
#pragma unroll
        for (int t = 0; t < 32; t++) {
            int s = __shfl_sync(0xFFFFFFFFu, my, t);
            float4 v = hpv[(size_t)s * 32 + lane];
            if (t & 1) { a1.x += v.x; a1.y += v.y; a1.z += v.z; a1.w += v.w; }
            else       { a0.x += v.x; a0.y += v.y; a0.z += v.z; a0.w += v.w; }
        }
    }
    if (j < k) {
        int idx = j + lane;
        int my = (idx < k) ? g_srcs[start + idx] : 0;
        int m = k - j;
        for (int t = 0; t < m; t++) {
            int s = __shfl_sync(0xFFFFFFFFu, my, t);
            float4 v = hpv[(size_t)s * 32 + lane];
            if (t & 1) { a1.x += v.x; a1.y += v.y; a1.z += v.z; a1.w += v.w; }
            else       { a0.x += v.x; a0.y += v.y; a0.z += v.z; a0.w += v.w; }
        }
    }

    float sd = g_dis[warp];
    float4 b = ((const float4*)bias)[lane];
    float4 o;
    o.x = fmaf(sd, a0.x + a1.x, b.x);
    o.y = fmaf(sd, a0.y + a1.y, b.y);
    o.z = fmaf(sd, a0.z + a1.z, b.z);
    o.w = fmaf(sd, a0.w + a1.w, b.w);
    ((float4*)out)[(size_t)warp * 32 + lane] = o;
}

// ---------------------------------------------------------------------------
// 9. zero any padding tail of d_out
// ---------------------------------------------------------------------------
__global__ void zero_tail_kernel(float* out, int begin, int end) {
    int i = begin + blockIdx.x * blockDim.x + threadIdx.x;
    if (i < end) out[i] = 0.f;
}

// ---------------------------------------------------------------------------
extern "C" void kernel_launch(void* const* d_in, const int* in_sizes, int n_in,
                              void* d_out, int out_size) {
    const float* x    = (const float*)d_in[0];
    const int*   ei   = (const int*)d_in[1];     // raw words; dtype detected on device
    const float* w    = (const float*)d_in[2];
    const float* bias = (const float*)d_in[3];
    float*       out  = (float*)d_out;

    const int n = in_sizes[0] / D;     // 100000
    const int e = in_sizes[1] / 2;     // 3200000

    const int chunk = (n + NSCAN - 1) / NSCAN;

    // dtype detect + CSR build
    detect_kernel<<<1, 256>>>(ei);
    zero_cnt_kernel<<<(n + 255) / 256, 256>>>(n);
    hist_kernel<<<2048, 256>>>(ei, e, n);
    scanA_kernel<<<NSCAN / 256, 256>>>(n, chunk);
    scanB_kernel<<<1, 1024>>>();
    scanC_kernel<<<NSCAN / 256, 256>>>(n, chunk);
    fill_kernel<<<2048, 256>>>(ei, e, n);

    // dense transform (needs g_dis)
    gemm_kernel<<<(n + TM - 1) / TM, 256>>>(x, w, n);

    // gather aggregation with fused finalize
    {
        long long total_threads = (long long)n * 32;
        int blocks = (int)((total_threads + 255) / 256);
        aggregate_kernel<<<blocks, 256>>>(bias, out, n);
    }

    // padding tail, if any
    if (out_size > n * D) {
        int extra = out_size - n * D;
        zero_tail_kernel<<<(extra + 255) / 256, 256>>>(out, n * D, out_size);
    }
}